// round 4
// baseline (speedup 1.0000x reference)
#include <cuda_runtime.h>

// Fixed problem shape
#define BB 256
#define TT 4096
#define CC 16
#define HH 20
#define GG 60
#define K  16             // steps per chunk
#define NC (TT / K)       // 256 chunks

typedef unsigned long long u64;

__device__ __forceinline__ u64 pack2(float a, float b) {
    u64 r; asm("mov.b64 %0,{%1,%2};" : "=l"(r) : "f"(a), "f"(b)); return r;
}
__device__ __forceinline__ void fma2(u64& d, u64 a, u64 b) {
    asm("fma.rn.f32x2 %0,%1,%2,%0;" : "+l"(d) : "l"(a), "l"(b));
}
__device__ __forceinline__ u64 add2(u64 a, u64 b) {
    u64 r; asm("add.rn.f32x2 %0,%1,%2;" : "=l"(r) : "l"(a), "l"(b)); return r;
}
__device__ __forceinline__ float hsum2(u64 v) {
    float x, y; asm("mov.b64 {%0,%1},%2;" : "=f"(x), "=f"(y) : "l"(v)); return x + y;
}
__device__ __forceinline__ float tanha(float x) {
    float y; asm("tanh.approx.f32 %0,%1;" : "=f"(y) : "f"(x)); return y;
}

// ---------------------------------------------------------------------------
// Fused 2-layer GRU, chunked 4-stage pipeline, 2 batches (A,B) per block.
// SMSP pairing (w%4) groups latency-bound warps together and throughput
// warps together so chain warps never fight a GX warp for issue slots:
//   S0: w0=L0(A)  w4=L1(B)      (chain + chain)
//   S1: w1=L1(A)  w5=L0(B)      (chain + chain)
//   S2: w2=GX0(A) w6=GX1(A)     (throughput, batch A)
//   S3: w3=GX0(B) w7=GX1(B)     (throughput, batch B)
// Stage lags: GX0 at chunk c, L0 at c-1, GX1 at c-2, L1 at c-3.
// r/z gate weights+biases and the r/z gx rows are pre-scaled by 0.5 so
// sigmoid(s) = fma(tanh.approx(0.5*s), 0.5, 0.5) needs no chain-side mul.
// ---------------------------------------------------------------------------
__global__ void __launch_bounds__(256, 1)
fused_gru_kernel(const float* __restrict__ x,      // [B,T,C]
                 const float* __restrict__ h0in,   // [B,2,H]
                 const float* __restrict__ W_ih0, const float* __restrict__ W_hh0,
                 const float* __restrict__ b_ih0, const float* __restrict__ b_hh0,
                 const float* __restrict__ W_ih1, const float* __restrict__ W_hh1,
                 const float* __restrict__ b_ih1, const float* __restrict__ b_hh1,
                 const float* __restrict__ W_o,   const float* __restrict__ b_o,
                 float* __restrict__ out)          // o[B*T] then h_n[B,2,H]
{
    __shared__ float s_x  [2][2][K][CC];
    __shared__ float s_gx0[2][2][K][GG];
    __shared__ float s_gx1[2][2][K][GG];
    __shared__ float s_h0 [2][2][K][HH];

    const int tid = threadIdx.x;
    const int w   = tid >> 5;
    const int i   = tid & 31;
    const bool act = (i < HH);
    const unsigned FULL = 0xFFFFFFFFu;

    // role & batch decode (see SMSP map above)
    // roles: 0=L0, 1=L1, 2=GX0, 3=GX1
    int role, bs;
    switch (w) {
        case 0: role = 0; bs = 0; break;
        case 1: role = 1; bs = 0; break;
        case 2: role = 2; bs = 0; break;
        case 3: role = 2; bs = 1; break;
        case 4: role = 1; bs = 1; break;
        case 5: role = 0; bs = 1; break;
        case 6: role = 3; bs = 0; break;
        default: role = 3; bs = 1; break;
    }
    const int b = blockIdx.x * 2 + bs;
    const float* xb = x + (size_t)b * TT * CC;

    // ---- prime x chunk 0 (GX0 warps) ---------------------------------------
    if (role == 2) {
        const float4* src = (const float4*)xb;           // K*CC = 256 floats
        float4 v0 = src[i], v1 = src[i + 32];
        float4* dst = (float4*)&s_x[bs][0][0][0];
        dst[i] = v0; dst[i + 32] = v1;
    }
    __syncthreads();

    if (role == 2) {
        // -------- GX0: gx0 = W_ih0 . x_t + b_ih0 (r,z rows pre-scaled 0.5) ----
        u64 wp[24];
        float br = 0.f, bz = 0.f, bn = 0.f;
#pragma unroll
        for (int g = 0; g < 3; ++g) {
            const float sc = (g < 2) ? 0.5f : 1.0f;
#pragma unroll
            for (int k = 0; k < 8; ++k)
                wp[g * 8 + k] = act ? pack2(sc * W_ih0[(g * HH + i) * CC + 2 * k],
                                            sc * W_ih0[(g * HH + i) * CC + 2 * k + 1])
                                    : pack2(0.f, 0.f);
        }
        if (act) { br = 0.5f * b_ih0[i]; bz = 0.5f * b_ih0[HH + i]; bn = b_ih0[2 * HH + i]; }

        for (int c = 0; c < NC + 3; ++c) {
            if (c + 1 < NC) {           // prefetch x chunk c+1
                const float4* src = (const float4*)(xb + (size_t)(c + 1) * K * CC);
                float4 v0 = src[i], v1 = src[i + 32];
                float4* dst = (float4*)&s_x[bs][(c + 1) & 1][0][0];
                dst[i] = v0; dst[i + 32] = v1;
            }
            if (c < NC) {
                const float* xs = &s_x[bs][c & 1][0][0];
                float* go = &s_gx0[bs][c & 1][0][0];
#pragma unroll 4
                for (int s = 0; s < K; ++s) {
                    u64 ar = pack2(br, 0.f), az = pack2(bz, 0.f), an = pack2(bn, 0.f);
                    const float* xr = xs + s * CC;
#pragma unroll
                    for (int k = 0; k < 8; ++k) {
                        u64 xv = *(const u64*)(xr + 2 * k);
                        fma2(ar, wp[k], xv);
                        fma2(az, wp[8 + k], xv);
                        fma2(an, wp[16 + k], xv);
                    }
                    if (act) {
                        go[s * GG + i]          = hsum2(ar);
                        go[s * GG + HH + i]     = hsum2(az);
                        go[s * GG + 2 * HH + i] = hsum2(an);
                    }
                }
            }
            __syncthreads();
        }
    } else if (role == 3) {
        // -------- GX1: gx1 = W_ih1 . h0_t + b_ih1 (r,z rows pre-scaled 0.5) ---
        u64 wp[30];
        float br = 0.f, bz = 0.f, bn = 0.f;
#pragma unroll
        for (int g = 0; g < 3; ++g) {
            const float sc = (g < 2) ? 0.5f : 1.0f;
#pragma unroll
            for (int k = 0; k < 10; ++k)
                wp[g * 10 + k] = act ? pack2(sc * W_ih1[(g * HH + i) * HH + 2 * k],
                                             sc * W_ih1[(g * HH + i) * HH + 2 * k + 1])
                                     : pack2(0.f, 0.f);
        }
        if (act) { br = 0.5f * b_ih1[i]; bz = 0.5f * b_ih1[HH + i]; bn = b_ih1[2 * HH + i]; }

        for (int c = 0; c < NC + 3; ++c) {
            const int cc = c - 2;
            if (cc >= 0 && cc < NC) {
                const float* hr = &s_h0[bs][cc & 1][0][0];
                float* go = &s_gx1[bs][cc & 1][0][0];
#pragma unroll 4
                for (int s = 0; s < K; ++s) {
                    u64 ar = pack2(br, 0.f), az = pack2(bz, 0.f), an = pack2(bn, 0.f);
                    const float* hrow = hr + s * HH;
#pragma unroll
                    for (int k = 0; k < 10; ++k) {
                        u64 hv = *(const u64*)(hrow + 2 * k);
                        fma2(ar, wp[k], hv);
                        fma2(az, wp[10 + k], hv);
                        fma2(an, wp[20 + k], hv);
                    }
                    if (act) {
                        go[s * GG + i]          = hsum2(ar);
                        go[s * GG + HH + i]     = hsum2(az);
                        go[s * GG + 2 * HH + i] = hsum2(an);
                    }
                }
            }
            __syncthreads();
        }
    } else {
        // -------- L0 / L1: recurrence (chain warps) ---------------------------
        const float* Whh = (role == 0) ? W_hh0 : W_hh1;
        const float* bhh = (role == 0) ? b_hh0 : b_hh1;
        const int lag    = (role == 0) ? 1 : 3;

        u64 wh[30];
        float br = 0.f, bz = 0.f, bn = 0.f, h = 0.f, wo = 0.f;
#pragma unroll
        for (int g = 0; g < 3; ++g) {
            const float sc = (g < 2) ? 0.5f : 1.0f;
#pragma unroll
            for (int k = 0; k < 10; ++k)
                wh[g * 10 + k] = act ? pack2(sc * Whh[(g * HH + i) * HH + 2 * k],
                                             sc * Whh[(g * HH + i) * HH + 2 * k + 1])
                                     : pack2(0.f, 0.f);
        }
        if (act) {
            br = 0.5f * bhh[i]; bz = 0.5f * bhh[HH + i]; bn = bhh[2 * HH + i];
            h = h0in[(b * 2 + role) * HH + i];
            if (role == 1) wo = W_o[i];
        }
        const float bo = b_o[0];
        float* ob = out + (size_t)b * TT;

        for (int c = 0; c < NC + 3; ++c) {
            const int cc = c - lag;
            if (cc >= 0 && cc < NC) {
                const float* gx = (role == 0) ? &s_gx0[bs][cc & 1][0][0]
                                              : &s_gx1[bs][cc & 1][0][0];
                float* hw = &s_h0[bs][cc & 1][0][0];
#pragma unroll 2
                for (int s = 0; s < K; ++s) {
                    float gr = 0.f, gz = 0.f, gn = 0.f;
                    if (act) {
                        gr = gx[s * GG + i];
                        gz = gx[s * GG + HH + i];
                        gn = gx[s * GG + 2 * HH + i];
                    }
                    u64 hp[10];
#pragma unroll
                    for (int k = 0; k < 10; ++k)
                        hp[k] = pack2(__shfl_sync(FULL, h, 2 * k),
                                      __shfl_sync(FULL, h, 2 * k + 1));
                    // dual accumulators per gate: chain depth 5
                    u64 ar0 = pack2(br, 0.f), az0 = pack2(bz, 0.f), an0 = pack2(bn, 0.f);
                    u64 ar1 = pack2(0.f, 0.f), az1 = pack2(0.f, 0.f), an1 = pack2(0.f, 0.f);
#pragma unroll
                    for (int k = 0; k < 5; ++k) {
                        fma2(ar0, wh[2*k],      hp[2*k]);
                        fma2(ar1, wh[2*k + 1],  hp[2*k + 1]);
                        fma2(az0, wh[10 + 2*k],     hp[2*k]);
                        fma2(az1, wh[10 + 2*k + 1], hp[2*k + 1]);
                        fma2(an0, wh[20 + 2*k],     hp[2*k]);
                        fma2(an1, wh[20 + 2*k + 1], hp[2*k + 1]);
                    }
                    const float r = fmaf(tanha(gr + hsum2(add2(ar0, ar1))), 0.5f, 0.5f);
                    const float z = fmaf(tanha(gz + hsum2(add2(az0, az1))), 0.5f, 0.5f);
                    const float n = tanha(fmaf(r, hsum2(add2(an0, an1)), gn));
                    h = fmaf(z, h - n, n);

                    if (role == 0) {
                        if (act) hw[s * HH + i] = h;
                    } else {
                        float v = h * wo;
                        v += __shfl_down_sync(FULL, v, 16);
                        v += __shfl_down_sync(FULL, v, 8);
                        v += __shfl_down_sync(FULL, v, 4);
                        v += __shfl_down_sync(FULL, v, 2);
                        v += __shfl_down_sync(FULL, v, 1);
                        if (i == 0) ob[cc * K + s] = v + bo;
                    }
                }
            }
            __syncthreads();
        }
        if (act) out[(size_t)BB * TT + (b * 2 + role) * HH + i] = h;
    }
}

// ---------------------------------------------------------------------------
extern "C" void kernel_launch(void* const* d_in, const int* in_sizes, int n_in,
                              void* d_out, int out_size) {
    const float* x     = (const float*)d_in[0];
    const float* h0    = (const float*)d_in[1];
    const float* W_ih0 = (const float*)d_in[2];
    const float* W_hh0 = (const float*)d_in[3];
    const float* b_ih0 = (const float*)d_in[4];
    const float* b_hh0 = (const float*)d_in[5];
    const float* W_ih1 = (const float*)d_in[6];
    const float* W_hh1 = (const float*)d_in[7];
    const float* b_ih1 = (const float*)d_in[8];
    const float* b_hh1 = (const float*)d_in[9];
    const float* W_o   = (const float*)d_in[10];
    const float* b_o   = (const float*)d_in[11];

    fused_gru_kernel<<<BB / 2, 256>>>(x, h0, W_ih0, W_hh0, b_ih0, b_hh0,
                                      W_ih1, W_hh1, b_ih1, b_hh1, W_o, b_o,
                                      (float*)d_out);
}

// round 5
// speedup vs baseline: 1.1125x; 1.1125x over previous
#include <cuda_runtime.h>

// Fixed problem shape
#define BB 256
#define TT 4096
#define CC 16
#define HH 20
#define GG 60
#define K  16             // steps per chunk
#define NC (TT / K)       // 256 chunks

typedef unsigned long long u64;

__device__ __forceinline__ u64 pack2(float a, float b) {
    u64 r; asm("mov.b64 %0,{%1,%2};" : "=l"(r) : "f"(a), "f"(b)); return r;
}
__device__ __forceinline__ void fma2(u64& d, u64 a, u64 b) {
    asm("fma.rn.f32x2 %0,%1,%2,%0;" : "+l"(d) : "l"(a), "l"(b));
}
__device__ __forceinline__ u64 add2(u64 a, u64 b) {
    u64 r; asm("add.rn.f32x2 %0,%1,%2;" : "=l"(r) : "l"(a), "l"(b)); return r;
}
__device__ __forceinline__ float hsum2(u64 v) {
    float x, y; asm("mov.b64 {%0,%1},%2;" : "=f"(x), "=f"(y) : "l"(v)); return x + y;
}
__device__ __forceinline__ float tanha(float x) {
    float y; asm("tanh.approx.f32 %0,%1;" : "=f"(y) : "f"(x)); return y;
}

// ---------------------------------------------------------------------------
// Fused 2-layer GRU, chunked 4-stage pipeline, 2 batches (A,B) per block.
//
// ARBITER-AWARE warp map (B300 intra-SMSP arbitration is highest-wid-first):
// every SMSP (= w%4) hosts ONE throughput GX warp at LOW wid and ONE
// latency-critical chain warp at HIGH wid, so the chain warp always wins
// arbitration and the GX warp mops up its stall shadows.
//   wid:   0        1        2        3        4       5       6       7
//   role:  GX0(A)   GX0(B)   GX1(A)   GX1(B)   L0(A)   L0(B)   L1(A)   L1(B)
//   SMSP:  0        1        2        3        0       1       2       3
// Decode: role = w>>1 (0=GX0,1=GX1,2=L0,3=L1), batch = w&1.
//
// Stage lags: GX0 at chunk c, L0 at c-1, GX1 at c-2, L1 at c-3.
// r/z gate weights+biases (incl. the gx rows) are pre-scaled by 0.5 so
// sigmoid(s) = fma(tanh.approx(0.5 s), 0.5, 0.5) with no chain-side mul.
// ---------------------------------------------------------------------------
__global__ void __launch_bounds__(256, 1)
fused_gru_kernel(const float* __restrict__ x,      // [B,T,C]
                 const float* __restrict__ h0in,   // [B,2,H]
                 const float* __restrict__ W_ih0, const float* __restrict__ W_hh0,
                 const float* __restrict__ b_ih0, const float* __restrict__ b_hh0,
                 const float* __restrict__ W_ih1, const float* __restrict__ W_hh1,
                 const float* __restrict__ b_ih1, const float* __restrict__ b_hh1,
                 const float* __restrict__ W_o,   const float* __restrict__ b_o,
                 float* __restrict__ out)          // o[B*T] then h_n[B,2,H]
{
    __shared__ float s_x  [2][2][K][CC];
    __shared__ float s_gx0[2][2][K][GG];
    __shared__ float s_gx1[2][2][K][GG];
    __shared__ float s_h0 [2][2][K][HH];

    const int tid = threadIdx.x;
    const int w   = tid >> 5;
    const int i   = tid & 31;
    const bool act = (i < HH);
    const unsigned FULL = 0xFFFFFFFFu;

    const int rc = w >> 1;     // 0=GX0, 1=GX1, 2=L0, 3=L1
    const int bs = w & 1;
    const int b  = blockIdx.x * 2 + bs;
    const float* xb = x + (size_t)b * TT * CC;

    // ---- prime x chunk 0 (GX0 warps) ---------------------------------------
    if (rc == 0) {
        const float4* src = (const float4*)xb;           // K*CC = 256 floats
        float4 v0 = src[i], v1 = src[i + 32];
        float4* dst = (float4*)&s_x[bs][0][0][0];
        dst[i] = v0; dst[i + 32] = v1;
    }
    __syncthreads();

    if (rc == 0) {
        // -------- GX0: gx0 = W_ih0 . x_t + b_ih0 (r,z rows pre-scaled 0.5) ----
        u64 wp[24];
        float br = 0.f, bz = 0.f, bn = 0.f;
#pragma unroll
        for (int g = 0; g < 3; ++g) {
            const float sc = (g < 2) ? 0.5f : 1.0f;
#pragma unroll
            for (int k = 0; k < 8; ++k)
                wp[g * 8 + k] = act ? pack2(sc * W_ih0[(g * HH + i) * CC + 2 * k],
                                            sc * W_ih0[(g * HH + i) * CC + 2 * k + 1])
                                    : pack2(0.f, 0.f);
        }
        if (act) { br = 0.5f * b_ih0[i]; bz = 0.5f * b_ih0[HH + i]; bn = b_ih0[2 * HH + i]; }

        for (int c = 0; c < NC + 3; ++c) {
            if (c + 1 < NC) {           // prefetch x chunk c+1
                const float4* src = (const float4*)(xb + (size_t)(c + 1) * K * CC);
                float4 v0 = src[i], v1 = src[i + 32];
                float4* dst = (float4*)&s_x[bs][(c + 1) & 1][0][0];
                dst[i] = v0; dst[i + 32] = v1;
            }
            if (c < NC) {
                const float* xs = &s_x[bs][c & 1][0][0];
                float* go = &s_gx0[bs][c & 1][0][0];
#pragma unroll 4
                for (int s = 0; s < K; ++s) {
                    u64 ar = pack2(br, 0.f), az = pack2(bz, 0.f), an = pack2(bn, 0.f);
                    const float* xr = xs + s * CC;
#pragma unroll
                    for (int k = 0; k < 8; ++k) {
                        u64 xv = *(const u64*)(xr + 2 * k);
                        fma2(ar, wp[k], xv);
                        fma2(az, wp[8 + k], xv);
                        fma2(an, wp[16 + k], xv);
                    }
                    if (act) {
                        go[s * GG + i]          = hsum2(ar);
                        go[s * GG + HH + i]     = hsum2(az);
                        go[s * GG + 2 * HH + i] = hsum2(an);
                    }
                }
            }
            __syncthreads();
        }
    } else if (rc == 1) {
        // -------- GX1: gx1 = W_ih1 . h0_t + b_ih1 (r,z rows pre-scaled 0.5) ---
        u64 wp[30];
        float br = 0.f, bz = 0.f, bn = 0.f;
#pragma unroll
        for (int g = 0; g < 3; ++g) {
            const float sc = (g < 2) ? 0.5f : 1.0f;
#pragma unroll
            for (int k = 0; k < 10; ++k)
                wp[g * 10 + k] = act ? pack2(sc * W_ih1[(g * HH + i) * HH + 2 * k],
                                             sc * W_ih1[(g * HH + i) * HH + 2 * k + 1])
                                     : pack2(0.f, 0.f);
        }
        if (act) { br = 0.5f * b_ih1[i]; bz = 0.5f * b_ih1[HH + i]; bn = b_ih1[2 * HH + i]; }

        for (int c = 0; c < NC + 3; ++c) {
            const int cc = c - 2;
            if (cc >= 0 && cc < NC) {
                const float* hr = &s_h0[bs][cc & 1][0][0];
                float* go = &s_gx1[bs][cc & 1][0][0];
#pragma unroll 4
                for (int s = 0; s < K; ++s) {
                    u64 ar = pack2(br, 0.f), az = pack2(bz, 0.f), an = pack2(bn, 0.f);
                    const float* hrow = hr + s * HH;
#pragma unroll
                    for (int k = 0; k < 10; ++k) {
                        u64 hv = *(const u64*)(hrow + 2 * k);
                        fma2(ar, wp[k], hv);
                        fma2(az, wp[10 + k], hv);
                        fma2(an, wp[20 + k], hv);
                    }
                    if (act) {
                        go[s * GG + i]          = hsum2(ar);
                        go[s * GG + HH + i]     = hsum2(az);
                        go[s * GG + 2 * HH + i] = hsum2(an);
                    }
                }
            }
            __syncthreads();
        }
    } else {
        // -------- L0 / L1: recurrence (chain warps, high wid = priority) ------
        const bool isL0  = (rc == 2);
        const float* Whh = isL0 ? W_hh0 : W_hh1;
        const float* bhh = isL0 ? b_hh0 : b_hh1;
        const int lag    = isL0 ? 1 : 3;
        const int layer  = isL0 ? 0 : 1;

        u64 wh[30];
        float br = 0.f, bz = 0.f, bn = 0.f, h = 0.f, wo = 0.f;
#pragma unroll
        for (int g = 0; g < 3; ++g) {
            const float sc = (g < 2) ? 0.5f : 1.0f;
#pragma unroll
            for (int k = 0; k < 10; ++k)
                wh[g * 10 + k] = act ? pack2(sc * Whh[(g * HH + i) * HH + 2 * k],
                                             sc * Whh[(g * HH + i) * HH + 2 * k + 1])
                                     : pack2(0.f, 0.f);
        }
        if (act) {
            br = 0.5f * bhh[i]; bz = 0.5f * bhh[HH + i]; bn = bhh[2 * HH + i];
            h = h0in[(b * 2 + layer) * HH + i];
            if (!isL0) wo = W_o[i];
        }
        const float bo = b_o[0];
        float* ob = out + (size_t)b * TT;

        for (int c = 0; c < NC + 3; ++c) {
            const int cc = c - lag;
            if (cc >= 0 && cc < NC) {
                const float* gx = isL0 ? &s_gx0[bs][cc & 1][0][0]
                                       : &s_gx1[bs][cc & 1][0][0];
                float* hw = &s_h0[bs][cc & 1][0][0];
#pragma unroll 2
                for (int s = 0; s < K; ++s) {
                    float gr = 0.f, gz = 0.f, gn = 0.f;
                    if (act) {
                        gr = gx[s * GG + i];
                        gz = gx[s * GG + HH + i];
                        gn = gx[s * GG + 2 * HH + i];
                    }
                    u64 hp[10];
#pragma unroll
                    for (int k = 0; k < 10; ++k)
                        hp[k] = pack2(__shfl_sync(FULL, h, 2 * k),
                                      __shfl_sync(FULL, h, 2 * k + 1));
                    // dual accumulators per gate: fma chain depth 5
                    u64 ar0 = pack2(br, 0.f), az0 = pack2(bz, 0.f), an0 = pack2(bn, 0.f);
                    u64 ar1 = pack2(0.f, 0.f), az1 = pack2(0.f, 0.f), an1 = pack2(0.f, 0.f);
#pragma unroll
                    for (int k = 0; k < 5; ++k) {
                        fma2(ar0, wh[2*k],          hp[2*k]);
                        fma2(ar1, wh[2*k + 1],      hp[2*k + 1]);
                        fma2(az0, wh[10 + 2*k],     hp[2*k]);
                        fma2(az1, wh[10 + 2*k + 1], hp[2*k + 1]);
                        fma2(an0, wh[20 + 2*k],     hp[2*k]);
                        fma2(an1, wh[20 + 2*k + 1], hp[2*k + 1]);
                    }
                    const float r = fmaf(tanha(gr + hsum2(add2(ar0, ar1))), 0.5f, 0.5f);
                    const float z = fmaf(tanha(gz + hsum2(add2(az0, az1))), 0.5f, 0.5f);
                    const float n = tanha(fmaf(r, hsum2(add2(an0, an1)), gn));
                    h = fmaf(z, h - n, n);

                    if (isL0) {
                        if (act) hw[s * HH + i] = h;
                    } else {
                        float v = h * wo;
                        v += __shfl_down_sync(FULL, v, 16);
                        v += __shfl_down_sync(FULL, v, 8);
                        v += __shfl_down_sync(FULL, v, 4);
                        v += __shfl_down_sync(FULL, v, 2);
                        v += __shfl_down_sync(FULL, v, 1);
                        if (i == 0) ob[cc * K + s] = v + bo;
                    }
                }
            }
            __syncthreads();
        }
        if (act) out[(size_t)BB * TT + (b * 2 + layer) * HH + i] = h;
    }
}

// ---------------------------------------------------------------------------
extern "C" void kernel_launch(void* const* d_in, const int* in_sizes, int n_in,
                              void* d_out, int out_size) {
    const float* x     = (const float*)d_in[0];
    const float* h0    = (const float*)d_in[1];
    const float* W_ih0 = (const float*)d_in[2];
    const float* W_hh0 = (const float*)d_in[3];
    const float* b_ih0 = (const float*)d_in[4];
    const float* b_hh0 = (const float*)d_in[5];
    const float* W_ih1 = (const float*)d_in[6];
    const float* W_hh1 = (const float*)d_in[7];
    const float* b_ih1 = (const float*)d_in[8];
    const float* b_hh1 = (const float*)d_in[9];
    const float* W_o   = (const float*)d_in[10];
    const float* b_o   = (const float*)d_in[11];

    fused_gru_kernel<<<BB / 2, 256>>>(x, h0, W_ih0, W_hh0, b_ih0, b_hh0,
                                      W_ih1, W_hh1, b_ih1, b_hh1, W_o, b_o,
                                      (float*)d_out);
}

// round 6
// speedup vs baseline: 1.6652x; 1.4968x over previous
#include <cuda_runtime.h>

// Fixed problem shape
#define BB 256
#define TT 4096
#define CC 16
#define HH 20
#define GG 60
#define K  16             // steps per chunk
#define NC (TT / K)       // 256 chunks

typedef unsigned long long u64;

__device__ __forceinline__ u64 pack2(float a, float b) {
    u64 r; asm("mov.b64 %0,{%1,%2};" : "=l"(r) : "f"(a), "f"(b)); return r;
}
__device__ __forceinline__ void fma2(u64& d, u64 a, u64 b) {
    asm("fma.rn.f32x2 %0,%1,%2,%0;" : "+l"(d) : "l"(a), "l"(b));
}
__device__ __forceinline__ float hsum2(u64 v) {
    float x, y; asm("mov.b64 {%0,%1},%2;" : "=f"(x), "=f"(y) : "l"(v)); return x + y;
}
__device__ __forceinline__ float tanha(float x) {
    float y; asm("tanh.approx.f32 %0,%1;" : "=f"(y) : "f"(x)); return y;
}
__device__ __forceinline__ float siga(float x) {
    return fmaf(tanha(x * 0.5f), 0.5f, 0.5f);
}

// ---------------------------------------------------------------------------
// Fused 2-layer GRU, 3-stage chunked pipeline, 2 batches (A,B) per block.
// GX1 is FUSED into the L0 warp: the shuffle broadcast of h0_t needed for
// step t+1's recurrence dot is reused to compute gx1_t = W_ih1 . h0_t
// (off the critical chain), eliminating the GX1 warp, the s_h0 smem
// round-trip, and one chunk of pipeline lag.
//
// Warp map (6 warps, SMSP = w%4):
//   w0=GX0(A) S0   w1=GX0(B) S1   w2=L0(A) S2   w3=L0(B) S3
//   w4=L1(A)  S0   w5=L1(B)  S1
// L0 (heaviest: recurrence chain + fused gx1) runs SOLO on its SMSP.
// L1 shares with the light GX0 warp (L1 at higher wid).
// Stage lags: GX0 at chunk c, L0 at c-1, L1 at c-2.  Per-step math is
// identical to the round-3 kernel (single accumulator per gate).
// ---------------------------------------------------------------------------
__global__ void __launch_bounds__(192, 1)
fused_gru_kernel(const float* __restrict__ x,      // [B,T,C]
                 const float* __restrict__ h0in,   // [B,2,H]
                 const float* __restrict__ W_ih0, const float* __restrict__ W_hh0,
                 const float* __restrict__ b_ih0, const float* __restrict__ b_hh0,
                 const float* __restrict__ W_ih1, const float* __restrict__ W_hh1,
                 const float* __restrict__ b_ih1, const float* __restrict__ b_hh1,
                 const float* __restrict__ W_o,   const float* __restrict__ b_o,
                 float* __restrict__ out)          // o[B*T] then h_n[B,2,H]
{
    __shared__ float s_x  [2][2][K][CC];
    __shared__ float s_gx0[2][2][K][GG];
    __shared__ float s_gx1[2][2][K][GG];

    const int tid = threadIdx.x;
    const int w   = tid >> 5;
    const int i   = tid & 31;
    const bool act = (i < HH);
    const unsigned FULL = 0xFFFFFFFFu;

    const int rc = w >> 1;     // 0=GX0, 1=L0(+GX1), 2=L1
    const int bs = w & 1;
    const int b  = blockIdx.x * 2 + bs;
    const float* xb = x + (size_t)b * TT * CC;

    // ---- prime x chunk 0 (GX0 warps) ---------------------------------------
    if (rc == 0) {
        const float4* src = (const float4*)xb;           // K*CC = 256 floats
        float4 v0 = src[i], v1 = src[i + 32];
        float4* dst = (float4*)&s_x[bs][0][0][0];
        dst[i] = v0; dst[i + 32] = v1;
    }
    __syncthreads();

    if (rc == 0) {
        // -------- GX0: gx0 = W_ih0 . x_t + b_ih0 --------
        u64 wp[24];
        float br = 0.f, bz = 0.f, bn = 0.f;
#pragma unroll
        for (int g = 0; g < 3; ++g)
#pragma unroll
            for (int k = 0; k < 8; ++k)
                wp[g * 8 + k] = act ? pack2(W_ih0[(g * HH + i) * CC + 2 * k],
                                            W_ih0[(g * HH + i) * CC + 2 * k + 1])
                                    : pack2(0.f, 0.f);
        if (act) { br = b_ih0[i]; bz = b_ih0[HH + i]; bn = b_ih0[2 * HH + i]; }

        for (int c = 0; c < NC + 2; ++c) {
            if (c + 1 < NC) {           // prefetch x chunk c+1
                const float4* src = (const float4*)(xb + (size_t)(c + 1) * K * CC);
                float4 v0 = src[i], v1 = src[i + 32];
                float4* dst = (float4*)&s_x[bs][(c + 1) & 1][0][0];
                dst[i] = v0; dst[i + 32] = v1;
            }
            if (c < NC) {
                const float* xs = &s_x[bs][c & 1][0][0];
                float* go = &s_gx0[bs][c & 1][0][0];
#pragma unroll 4
                for (int s = 0; s < K; ++s) {
                    u64 ar = pack2(br, 0.f), az = pack2(bz, 0.f), an = pack2(bn, 0.f);
                    const float* xr = xs + s * CC;
#pragma unroll
                    for (int k = 0; k < 8; ++k) {
                        u64 xv = *(const u64*)(xr + 2 * k);
                        fma2(ar, wp[k], xv);
                        fma2(az, wp[8 + k], xv);
                        fma2(an, wp[16 + k], xv);
                    }
                    if (act) {
                        go[s * GG + i]          = hsum2(ar);
                        go[s * GG + HH + i]     = hsum2(az);
                        go[s * GG + 2 * HH + i] = hsum2(an);
                    }
                }
            }
            __syncthreads();
        }
    } else if (rc == 1) {
        // -------- L0 recurrence + fused GX1 --------
        u64 wh[30];   // W_hh0, packed pairs over j
        u64 wi[30];   // W_ih1, packed pairs over j
        float br = 0.f, bz = 0.f, bn = 0.f;       // b_hh0
        float cr_ = 0.f, cz_ = 0.f, cn_ = 0.f;    // b_ih1
        float h = 0.f;
#pragma unroll
        for (int g = 0; g < 3; ++g)
#pragma unroll
            for (int k = 0; k < 10; ++k) {
                wh[g * 10 + k] = act ? pack2(W_hh0[(g * HH + i) * HH + 2 * k],
                                             W_hh0[(g * HH + i) * HH + 2 * k + 1])
                                     : pack2(0.f, 0.f);
                wi[g * 10 + k] = act ? pack2(W_ih1[(g * HH + i) * HH + 2 * k],
                                             W_ih1[(g * HH + i) * HH + 2 * k + 1])
                                     : pack2(0.f, 0.f);
            }
        if (act) {
            br = b_hh0[i]; bz = b_hh0[HH + i]; bn = b_hh0[2 * HH + i];
            cr_ = b_ih1[i]; cz_ = b_ih1[HH + i]; cn_ = b_ih1[2 * HH + i];
            h = h0in[(b * 2 + 0) * HH + i];
        }

        // initial broadcast of h0 state
        u64 hp[10];
#pragma unroll
        for (int k = 0; k < 10; ++k)
            hp[k] = pack2(__shfl_sync(FULL, h, 2 * k),
                          __shfl_sync(FULL, h, 2 * k + 1));

        for (int c = 0; c < NC + 2; ++c) {
            const int cc = c - 1;
            if (cc >= 0 && cc < NC) {
                const float* gx = &s_gx0[bs][cc & 1][0][0];
                float* go = &s_gx1[bs][cc & 1][0][0];
#pragma unroll 2
                for (int s = 0; s < K; ++s) {
                    float gr = 0.f, gz = 0.f, gn = 0.f;
                    if (act) {
                        gr = gx[s * GG + i];
                        gz = gx[s * GG + HH + i];
                        gn = gx[s * GG + 2 * HH + i];
                    }
                    // recurrence dot (critical chain)
                    u64 ar = pack2(br, 0.f), az = pack2(bz, 0.f), an = pack2(bn, 0.f);
#pragma unroll
                    for (int k = 0; k < 10; ++k) {
                        fma2(ar, wh[k],      hp[k]);
                        fma2(az, wh[10 + k], hp[k]);
                        fma2(an, wh[20 + k], hp[k]);
                    }
                    const float r = siga(gr + hsum2(ar));
                    const float z = siga(gz + hsum2(az));
                    const float n = tanha(fmaf(r, hsum2(an), gn));
                    h = fmaf(z, h - n, n);

                    // broadcast new h (feeds next step's chain AND gx1 below)
#pragma unroll
                    for (int k = 0; k < 10; ++k)
                        hp[k] = pack2(__shfl_sync(FULL, h, 2 * k),
                                      __shfl_sync(FULL, h, 2 * k + 1));

                    // fused GX1: gx1[s] = W_ih1 . h0[s] + b_ih1 (off-chain)
                    u64 qr = pack2(cr_, 0.f), qz = pack2(cz_, 0.f), qn = pack2(cn_, 0.f);
#pragma unroll
                    for (int k = 0; k < 10; ++k) {
                        fma2(qr, wi[k],      hp[k]);
                        fma2(qz, wi[10 + k], hp[k]);
                        fma2(qn, wi[20 + k], hp[k]);
                    }
                    if (act) {
                        go[s * GG + i]          = hsum2(qr);
                        go[s * GG + HH + i]     = hsum2(qz);
                        go[s * GG + 2 * HH + i] = hsum2(qn);
                    }
                }
            }
            __syncthreads();
        }
        if (act) out[(size_t)BB * TT + (b * 2 + 0) * HH + i] = h;
    } else {
        // -------- L1 recurrence + output head --------
        u64 wh[30];
        float br = 0.f, bz = 0.f, bn = 0.f, h = 0.f, wo = 0.f;
#pragma unroll
        for (int g = 0; g < 3; ++g)
#pragma unroll
            for (int k = 0; k < 10; ++k)
                wh[g * 10 + k] = act ? pack2(W_hh1[(g * HH + i) * HH + 2 * k],
                                             W_hh1[(g * HH + i) * HH + 2 * k + 1])
                                     : pack2(0.f, 0.f);
        if (act) {
            br = b_hh1[i]; bz = b_hh1[HH + i]; bn = b_hh1[2 * HH + i];
            h = h0in[(b * 2 + 1) * HH + i];
            wo = W_o[i];
        }
        const float bo = b_o[0];
        float* ob = out + (size_t)b * TT;

        u64 hp[10];
#pragma unroll
        for (int k = 0; k < 10; ++k)
            hp[k] = pack2(__shfl_sync(FULL, h, 2 * k),
                          __shfl_sync(FULL, h, 2 * k + 1));

        for (int c = 0; c < NC + 2; ++c) {
            const int cc = c - 2;
            if (cc >= 0 && cc < NC) {
                const float* gx = &s_gx1[bs][cc & 1][0][0];
#pragma unroll 2
                for (int s = 0; s < K; ++s) {
                    float gr = 0.f, gz = 0.f, gn = 0.f;
                    if (act) {
                        gr = gx[s * GG + i];
                        gz = gx[s * GG + HH + i];
                        gn = gx[s * GG + 2 * HH + i];
                    }
                    u64 ar = pack2(br, 0.f), az = pack2(bz, 0.f), an = pack2(bn, 0.f);
#pragma unroll
                    for (int k = 0; k < 10; ++k) {
                        fma2(ar, wh[k],      hp[k]);
                        fma2(az, wh[10 + k], hp[k]);
                        fma2(an, wh[20 + k], hp[k]);
                    }
                    const float r = siga(gr + hsum2(ar));
                    const float z = siga(gz + hsum2(az));
                    const float n = tanha(fmaf(r, hsum2(an), gn));
                    h = fmaf(z, h - n, n);

#pragma unroll
                    for (int k = 0; k < 10; ++k)
                        hp[k] = pack2(__shfl_sync(FULL, h, 2 * k),
                                      __shfl_sync(FULL, h, 2 * k + 1));

                    // output head (off-chain)
                    float v = h * wo;
                    v += __shfl_down_sync(FULL, v, 16);
                    v += __shfl_down_sync(FULL, v, 8);
                    v += __shfl_down_sync(FULL, v, 4);
                    v += __shfl_down_sync(FULL, v, 2);
                    v += __shfl_down_sync(FULL, v, 1);
                    if (i == 0) ob[cc * K + s] = v + bo;
                }
            }
            __syncthreads();
        }
        if (act) out[(size_t)BB * TT + (b * 2 + 1) * HH + i] = h;
    }
}

// ---------------------------------------------------------------------------
extern "C" void kernel_launch(void* const* d_in, const int* in_sizes, int n_in,
                              void* d_out, int out_size) {
    const float* x     = (const float*)d_in[0];
    const float* h0    = (const float*)d_in[1];
    const float* W_ih0 = (const float*)d_in[2];
    const float* W_hh0 = (const float*)d_in[3];
    const float* b_ih0 = (const float*)d_in[4];
    const float* b_hh0 = (const float*)d_in[5];
    const float* W_ih1 = (const float*)d_in[6];
    const float* W_hh1 = (const float*)d_in[7];
    const float* b_ih1 = (const float*)d_in[8];
    const float* b_hh1 = (const float*)d_in[9];
    const float* W_o   = (const float*)d_in[10];
    const float* b_o   = (const float*)d_in[11];

    fused_gru_kernel<<<BB / 2, 192>>>(x, h0, W_ih0, W_hh0, b_ih0, b_hh0,
                                      W_ih1, W_hh1, b_ih1, b_hh1, W_o, b_o,
                                      (float*)d_out);
}